// round 2
// baseline (speedup 1.0000x reference)
#include <cuda_runtime.h>
#include <cstdint>
#include <cstddef>

// Problem dims (fixed by the dataset)
#define M_DIM   8192      // 4*2048 rows of x
#define IN_DIM  4096      // K of main GEMM
#define OUT_DIM 11008     // N of main GEMM
#define RANK_   192

// ---------------------------------------------------------------------------
// Scratch (static __device__ arrays — allocation-free per harness rules)
// ---------------------------------------------------------------------------
__device__ float g_x    [(size_t)M_DIM  * IN_DIM];   // tf32-rounded x
__device__ float g_w    [(size_t)OUT_DIM * IN_DIM];  // weight+delta (fp32), then quantized tf32
__device__ float g_bd_hi[(size_t)OUT_DIM * RANK_];
__device__ float g_bd_lo[(size_t)OUT_DIM * RANK_];
__device__ float g_bu_hi[(size_t)RANK_  * IN_DIM];
__device__ float g_bu_lo[(size_t)RANK_  * IN_DIM];

__device__ __forceinline__ float to_tf32(float x) {
    uint32_t u;
    asm("cvt.rna.tf32.f32 %0, %1;" : "=r"(u) : "f"(x));
    return __uint_as_float(u);
}

// ---------------------------------------------------------------------------
// Elementwise tf32 rounding (float4 vectorized; all sizes divisible by 4)
// ---------------------------------------------------------------------------
__global__ void cvt_tf32_kernel(const float* __restrict__ in,
                                float* __restrict__ out, int n4) {
    int i = blockIdx.x * 256 + threadIdx.x;
    if (i < n4) {
        float4 v = reinterpret_cast<const float4*>(in)[i];
        v.x = to_tf32(v.x); v.y = to_tf32(v.y);
        v.z = to_tf32(v.z); v.w = to_tf32(v.w);
        reinterpret_cast<float4*>(out)[i] = v;
    }
}

// Split v = hi + lo, hi = tf32(v), lo = tf32(v - hi).  Residual ~2^-22 rel.
__global__ void cvt_split_kernel(const float* __restrict__ in,
                                 float* __restrict__ hi,
                                 float* __restrict__ lo, int n4) {
    int i = blockIdx.x * 256 + threadIdx.x;
    if (i < n4) {
        float4 v = reinterpret_cast<const float4*>(in)[i];
        float4 h, l;
        h.x = to_tf32(v.x); l.x = to_tf32(v.x - h.x);
        h.y = to_tf32(v.y); l.y = to_tf32(v.y - h.y);
        h.z = to_tf32(v.z); l.z = to_tf32(v.z - h.z);
        h.w = to_tf32(v.w); l.w = to_tf32(v.w - h.w);
        reinterpret_cast<float4*>(hi)[i] = h;
        reinterpret_cast<float4*>(lo)[i] = l;
    }
}

// ---------------------------------------------------------------------------
// Row-wise 4-bit asymmetric fake quant, in place on g_w (fp32 in, tf32 out).
// ---------------------------------------------------------------------------
__global__ void quant_kernel(float* __restrict__ w) {
    const int row = blockIdx.x;
    float* p = w + (size_t)row * IN_DIM;
    const int tid = threadIdx.x;

    float mn = 0.0f, mx = 0.0f;   // init 0 implements the min/max-with-0 clamp
    #pragma unroll
    for (int i = tid; i < IN_DIM / 4; i += 256) {
        float4 v = reinterpret_cast<float4*>(p)[i];
        mn = fminf(mn, fminf(fminf(v.x, v.y), fminf(v.z, v.w)));
        mx = fmaxf(mx, fmaxf(fmaxf(v.x, v.y), fmaxf(v.z, v.w)));
    }
    #pragma unroll
    for (int o = 16; o; o >>= 1) {
        mn = fminf(mn, __shfl_xor_sync(0xffffffffu, mn, o));
        mx = fmaxf(mx, __shfl_xor_sync(0xffffffffu, mx, o));
    }
    __shared__ float smn[8], smx[8];
    __shared__ float s_scale, s_zero;
    const int warp = tid >> 5, lane = tid & 31;
    if (lane == 0) { smn[warp] = mn; smx[warp] = mx; }
    __syncthreads();
    if (tid == 0) {
        float a = smn[0], b = smx[0];
        #pragma unroll
        for (int i = 1; i < 8; i++) { a = fminf(a, smn[i]); b = fmaxf(b, smx[i]); }
        float sc = fmaxf((b - a) / 15.0f, 1e-8f);
        s_scale = sc;
        s_zero  = rintf(-a / sc);
    }
    __syncthreads();
    const float sc = s_scale, z = s_zero;

    #pragma unroll
    for (int i = tid; i < IN_DIM / 4; i += 256) {
        float4 v = reinterpret_cast<float4*>(p)[i];
        float q;
        q = fminf(fmaxf(rintf(v.x / sc) + z, 0.0f), 15.0f); v.x = to_tf32((q - z) * sc);
        q = fminf(fmaxf(rintf(v.y / sc) + z, 0.0f), 15.0f); v.y = to_tf32((q - z) * sc);
        q = fminf(fmaxf(rintf(v.z / sc) + z, 0.0f), 15.0f); v.z = to_tf32((q - z) * sc);
        q = fminf(fmaxf(rintf(v.w / sc) + z, 0.0f), 15.0f); v.w = to_tf32((q - z) * sc);
        reinterpret_cast<float4*>(p)[i] = v;
    }
}

// ---------------------------------------------------------------------------
// TF32 GEMM via mma.sync.m16n8k8:  D[M,N] = A[M,K] * B + epilogue
//   BLAY=0: B is [N,K] row-major (K contiguous)   — main GEMM (B = w)
//   BLAY=1: B is [K,N] row-major (N contiguous)   — delta GEMM (B = Bu)
//   EPI=0 : D = acc + C[M,N]  (C may alias D; per-thread read-then-write)
//   EPI=1 : D = acc + C[N]    (C = bias)
// Block tile 128x128x32, 256 threads = 8 warps (4M x 2N), warp tile 32x64.
// ---------------------------------------------------------------------------
#define BK       32
#define ASTRIDE  36            // 128x32 tile rows padded to 36 (conflict-free)
#define BSTRIDE_KN 136         // 32x128 tile rows padded to 136
#define ASZ (128 * ASTRIDE)    // 4608 floats
#define BSZ (128 * ASTRIDE)    // covers both layouts (KN needs 32*136=4352)
#define SMEM_BYTES ((2 * ASZ + 2 * BSZ) * 4)   // 73728

__device__ __forceinline__ void cp16(uint32_t s, const float* g) {
    asm volatile("cp.async.cg.shared.global [%0], [%1], 16;\n" :: "r"(s), "l"(g));
}

template <int BLAY, int EPI>
__global__ __launch_bounds__(256, 2)
void gemm_tf32(const float* __restrict__ A, const float* __restrict__ B,
               const float* __restrict__ C, float* __restrict__ D,
               int M, int N, int K) {
    extern __shared__ float sm[];
    float* As = sm;
    float* Bs = sm + 2 * ASZ;

    const int tid  = threadIdx.x;
    const int lane = tid & 31, warp = tid >> 5;
    const int grp  = lane >> 2, tig = lane & 3;
    const int wm   = warp & 3,  wn  = warp >> 2;
    const int mBase = blockIdx.y * 128, nBase = blockIdx.x * 128;

    const uint32_t sA = (uint32_t)__cvta_generic_to_shared(As);
    const uint32_t sB = (uint32_t)__cvta_generic_to_shared(Bs);

    float acc[2][8][4];
    #pragma unroll
    for (int i = 0; i < 2; i++)
        #pragma unroll
        for (int j = 0; j < 8; j++)
            #pragma unroll
            for (int k = 0; k < 4; k++) acc[i][j][k] = 0.0f;

    const int KT = K / BK;

    auto issue_tile = [&](int kt, int buf) {
        const float* ga = A + (size_t)mBase * K + (size_t)kt * BK;
        #pragma unroll
        for (int i = 0; i < 4; i++) {
            int idx = tid + i * 256;
            int r = idx >> 3, c = (idx & 7) << 2;        // 8 float4 per 32-col row
            cp16(sA + (uint32_t)((buf * ASZ + r * ASTRIDE + c) << 2),
                 ga + (size_t)r * K + c);
        }
        if (BLAY == 0) {
            const float* gb = B + (size_t)nBase * K + (size_t)kt * BK;
            #pragma unroll
            for (int i = 0; i < 4; i++) {
                int idx = tid + i * 256;
                int r = idx >> 3, c = (idx & 7) << 2;
                cp16(sB + (uint32_t)((buf * BSZ + r * ASTRIDE + c) << 2),
                     gb + (size_t)r * K + c);
            }
        } else {
            const float* gb = B + (size_t)(kt * BK) * N + nBase;
            #pragma unroll
            for (int i = 0; i < 4; i++) {
                int idx = tid + i * 256;
                int k = idx >> 5, c = (idx & 31) << 2;   // 32 float4 per 128-col row
                cp16(sB + (uint32_t)((buf * BSZ + k * BSTRIDE_KN + c) << 2),
                     gb + (size_t)k * N + c);
            }
        }
        asm volatile("cp.async.commit_group;\n");
    };

    issue_tile(0, 0);

    for (int kt = 0; kt < KT; ++kt) {
        const int buf = kt & 1;
        if (kt + 1 < KT) {
            issue_tile(kt + 1, buf ^ 1);
            asm volatile("cp.async.wait_group 1;\n");
        } else {
            asm volatile("cp.async.wait_group 0;\n");
        }
        __syncthreads();

        const float* a = As + buf * ASZ;
        const float* b = Bs + buf * BSZ;

        #pragma unroll
        for (int ks = 0; ks < 4; ++ks) {
            const int kb = ks * 8;
            uint32_t b0[8], b1[8];
            #pragma unroll
            for (int ni = 0; ni < 8; ++ni) {
                const int n = wn * 64 + ni * 8 + grp;
                if (BLAY == 0) {
                    b0[ni] = __float_as_uint(b[n * ASTRIDE + kb + tig]);
                    b1[ni] = __float_as_uint(b[n * ASTRIDE + kb + 4 + tig]);
                } else {
                    b0[ni] = __float_as_uint(b[(kb + tig)     * BSTRIDE_KN + n]);
                    b1[ni] = __float_as_uint(b[(kb + 4 + tig) * BSTRIDE_KN + n]);
                }
            }
            #pragma unroll
            for (int mi = 0; mi < 2; ++mi) {
                const int m = wm * 32 + mi * 16 + grp;
                uint32_t a0 = __float_as_uint(a[m       * ASTRIDE + kb + tig]);
                uint32_t a1 = __float_as_uint(a[(m + 8) * ASTRIDE + kb + tig]);
                uint32_t a2 = __float_as_uint(a[m       * ASTRIDE + kb + 4 + tig]);
                uint32_t a3 = __float_as_uint(a[(m + 8) * ASTRIDE + kb + 4 + tig]);
                #pragma unroll
                for (int ni = 0; ni < 8; ++ni) {
                    asm volatile(
                        "mma.sync.aligned.m16n8k8.row.col.f32.tf32.tf32.f32 "
                        "{%0,%1,%2,%3}, {%4,%5,%6,%7}, {%8,%9}, {%0,%1,%2,%3};\n"
                        : "+f"(acc[mi][ni][0]), "+f"(acc[mi][ni][1]),
                          "+f"(acc[mi][ni][2]), "+f"(acc[mi][ni][3])
                        : "r"(a0), "r"(a1), "r"(a2), "r"(a3),
                          "r"(b0[ni]), "r"(b1[ni]));
                }
            }
        }
        __syncthreads();
    }

    // Epilogue
    #pragma unroll
    for (int mi = 0; mi < 2; ++mi) {
        #pragma unroll
        for (int ni = 0; ni < 8; ++ni) {
            const int r0 = mBase + wm * 32 + mi * 16 + grp;
            const int cc = nBase + wn * 64 + ni * 8 + 2 * tig;
            float2 add0, add1;
            if (EPI == 0) {
                add0 = *reinterpret_cast<const float2*>(&C[(size_t)r0 * N + cc]);
                add1 = *reinterpret_cast<const float2*>(&C[(size_t)(r0 + 8) * N + cc]);
            } else {
                add0 = *reinterpret_cast<const float2*>(&C[cc]);
                add1 = add0;
            }
            float2 o0 = make_float2(acc[mi][ni][0] + add0.x, acc[mi][ni][1] + add0.y);
            float2 o1 = make_float2(acc[mi][ni][2] + add1.x, acc[mi][ni][3] + add1.y);
            *reinterpret_cast<float2*>(&D[(size_t)r0 * N + cc])       = o0;
            *reinterpret_cast<float2*>(&D[(size_t)(r0 + 8) * N + cc]) = o1;
        }
    }
}

// ---------------------------------------------------------------------------
// Launch
// ---------------------------------------------------------------------------
extern "C" void kernel_launch(void* const* d_in, const int* in_sizes, int n_in,
                              void* d_out, int out_size) {
    const float *x = nullptr, *weight = nullptr, *Bd = nullptr,
                *Bu = nullptr, *bias = nullptr;
    for (int i = 0; i < n_in; i++) {
        switch (in_sizes[i]) {
            case 33554432: x      = (const float*)d_in[i]; break;  // 8192*4096
            case 45088768: weight = (const float*)d_in[i]; break;  // 11008*4096
            case 2113536:  Bd     = (const float*)d_in[i]; break;  // 11008*192
            case 786432:   Bu     = (const float*)d_in[i]; break;  // 192*4096
            case 11008:    bias   = (const float*)d_in[i]; break;
        }
    }
    // Positional fallback (metadata order: x, weight, Bd, Bu, bias)
    if (!x && n_in > 0)      x      = (const float*)d_in[0];
    if (!weight && n_in > 1) weight = (const float*)d_in[1];
    if (!Bd && n_in > 2)     Bd     = (const float*)d_in[2];
    if (!Bu && n_in > 3)     Bu     = (const float*)d_in[3];
    if (!bias && n_in > 4)   bias   = (const float*)d_in[4];

    float *gx, *gw, *gbdh, *gbdl, *gbuh, *gbul;
    cudaGetSymbolAddress((void**)&gx,   g_x);
    cudaGetSymbolAddress((void**)&gw,   g_w);
    cudaGetSymbolAddress((void**)&gbdh, g_bd_hi);
    cudaGetSymbolAddress((void**)&gbdl, g_bd_lo);
    cudaGetSymbolAddress((void**)&gbuh, g_bu_hi);
    cudaGetSymbolAddress((void**)&gbul, g_bu_lo);

    cudaFuncSetAttribute(gemm_tf32<0, 1>,
                         cudaFuncAttributeMaxDynamicSharedMemorySize, SMEM_BYTES);
    cudaFuncSetAttribute(gemm_tf32<1, 0>,
                         cudaFuncAttributeMaxDynamicSharedMemorySize, SMEM_BYTES);

    // 1) tf32-round x; hi/lo split of Bd, Bu for 3xTF32 delta GEMM
    cvt_tf32_kernel <<<(33554432 / 4 + 255) / 256, 256>>>(x, gx, 33554432 / 4);
    cvt_split_kernel<<<(2113536  / 4 + 255) / 256, 256>>>(Bd, gbdh, gbdl, 2113536 / 4);
    cvt_split_kernel<<<(786432   / 4 + 255) / 256, 256>>>(Bu, gbuh, gbul, 786432  / 4);

    // 2) g_w = weight + Bd@Bu at fp32-equivalent precision (3xTF32):
    //    hi*hi + hi*lo + lo*hi   (lo*lo term ~2^-22 relative, dropped)
    //    M=11008, N=4096, K=192; B layout [K,N]
    dim3 dgrid(IN_DIM / 128, OUT_DIM / 128);
    gemm_tf32<1, 0><<<dgrid, 256, SMEM_BYTES>>>(gbdh, gbuh, weight, gw,
                                                OUT_DIM, IN_DIM, RANK_);
    gemm_tf32<1, 0><<<dgrid, 256, SMEM_BYTES>>>(gbdh, gbul, gw, gw,
                                                OUT_DIM, IN_DIM, RANK_);
    gemm_tf32<1, 0><<<dgrid, 256, SMEM_BYTES>>>(gbdl, gbuh, gw, gw,
                                                OUT_DIM, IN_DIM, RANK_);

    // 3) fake-quant each row of g_w in place (fp32 decisions, tf32 output)
    quant_kernel<<<OUT_DIM, 256>>>(gw);

    // 4) out = x @ w^T + bias      (M=8192, N=11008, K=4096; B layout [N,K])
    gemm_tf32<0, 1><<<dim3(OUT_DIM / 128, M_DIM / 128), 256, SMEM_BYTES>>>(
        gx, gw, bias, (float*)d_out, M_DIM, OUT_DIM, IN_DIM);
}

// round 4
// speedup vs baseline: 1.5789x; 1.5789x over previous
#include <cuda_runtime.h>
#include <cuda_fp16.h>
#include <cstdint>
#include <cstddef>

// Problem dims (fixed by the dataset)
#define M_DIM   8192      // 4*2048 rows of x
#define IN_DIM  4096      // K of main GEMM
#define OUT_DIM 11008     // N of main GEMM
#define RANK_   192

// ---------------------------------------------------------------------------
// Scratch (static __device__ arrays — allocation-free per harness rules)
// ---------------------------------------------------------------------------
__device__ __align__(256) float  g_w [(size_t)OUT_DIM * IN_DIM];  // weight+delta fp32
__device__ __align__(256) __half g_xh[(size_t)M_DIM  * IN_DIM];   // x as fp16
__device__ __align__(256) __half g_wh[(size_t)OUT_DIM * IN_DIM];  // quantized w as fp16
__device__ __align__(256) float  g_bd_hi[(size_t)OUT_DIM * RANK_];
__device__ __align__(256) float  g_bd_lo[(size_t)OUT_DIM * RANK_];
__device__ __align__(256) float  g_bu_hi[(size_t)RANK_  * IN_DIM];
__device__ __align__(256) float  g_bu_lo[(size_t)RANK_  * IN_DIM];

__device__ __forceinline__ float to_tf32(float x) {
    uint32_t u;
    asm("cvt.rna.tf32.f32 %0, %1;" : "=r"(u) : "f"(x));
    return __uint_as_float(u);
}

// ---------------------------------------------------------------------------
// Elementwise prep kernels
// ---------------------------------------------------------------------------
__global__ void cvt_half_kernel(const float* __restrict__ in,
                                __half* __restrict__ out, int n4) {
    int i = blockIdx.x * 256 + threadIdx.x;
    if (i < n4) {
        float4 v = reinterpret_cast<const float4*>(in)[i];
        __half2 h0 = __floats2half2_rn(v.x, v.y);
        __half2 h1 = __floats2half2_rn(v.z, v.w);
        uint2 p;
        p.x = *reinterpret_cast<uint32_t*>(&h0);
        p.y = *reinterpret_cast<uint32_t*>(&h1);
        reinterpret_cast<uint2*>(out)[i] = p;
    }
}

// Split v = hi + lo in tf32 (for 3xTF32 fp32-accurate delta GEMM)
__global__ void cvt_split_kernel(const float* __restrict__ in,
                                 float* __restrict__ hi,
                                 float* __restrict__ lo, int n4) {
    int i = blockIdx.x * 256 + threadIdx.x;
    if (i < n4) {
        float4 v = reinterpret_cast<const float4*>(in)[i];
        float4 h, l;
        h.x = to_tf32(v.x); l.x = to_tf32(v.x - h.x);
        h.y = to_tf32(v.y); l.y = to_tf32(v.y - h.y);
        h.z = to_tf32(v.z); l.z = to_tf32(v.z - h.z);
        h.w = to_tf32(v.w); l.w = to_tf32(v.w - h.w);
        reinterpret_cast<float4*>(hi)[i] = h;
        reinterpret_cast<float4*>(lo)[i] = l;
    }
}

// ---------------------------------------------------------------------------
// Row-wise 4-bit asymmetric fake quant: read fp32 g_w, emit fp16 g_wh.
// Quant decisions in fp32 (exact vs reference); output rounding 2^-11.
// ---------------------------------------------------------------------------
__global__ void quant_kernel(const float* __restrict__ w, __half* __restrict__ wh) {
    const int row = blockIdx.x;
    const float* p = w + (size_t)row * IN_DIM;
    __half* po = wh + (size_t)row * IN_DIM;
    const int tid = threadIdx.x;

    float mn = 0.0f, mx = 0.0f;   // init 0 implements min/max-with-0 clamp
    #pragma unroll
    for (int i = tid; i < IN_DIM / 4; i += 256) {
        float4 v = reinterpret_cast<const float4*>(p)[i];
        mn = fminf(mn, fminf(fminf(v.x, v.y), fminf(v.z, v.w)));
        mx = fmaxf(mx, fmaxf(fmaxf(v.x, v.y), fmaxf(v.z, v.w)));
    }
    #pragma unroll
    for (int o = 16; o; o >>= 1) {
        mn = fminf(mn, __shfl_xor_sync(0xffffffffu, mn, o));
        mx = fmaxf(mx, __shfl_xor_sync(0xffffffffu, mx, o));
    }
    __shared__ float smn[8], smx[8];
    __shared__ float s_scale, s_zero;
    const int warp = tid >> 5, lane = tid & 31;
    if (lane == 0) { smn[warp] = mn; smx[warp] = mx; }
    __syncthreads();
    if (tid == 0) {
        float a = smn[0], b = smx[0];
        #pragma unroll
        for (int i = 1; i < 8; i++) { a = fminf(a, smn[i]); b = fmaxf(b, smx[i]); }
        float sc = fmaxf((b - a) / 15.0f, 1e-8f);
        s_scale = sc;
        s_zero  = rintf(-a / sc);
    }
    __syncthreads();
    const float sc = s_scale, z = s_zero;

    #pragma unroll
    for (int i = tid; i < IN_DIM / 4; i += 256) {
        float4 v = reinterpret_cast<const float4*>(p)[i];
        float q0 = (fminf(fmaxf(rintf(v.x / sc) + z, 0.0f), 15.0f) - z) * sc;
        float q1 = (fminf(fmaxf(rintf(v.y / sc) + z, 0.0f), 15.0f) - z) * sc;
        float q2 = (fminf(fmaxf(rintf(v.z / sc) + z, 0.0f), 15.0f) - z) * sc;
        float q3 = (fminf(fmaxf(rintf(v.w / sc) + z, 0.0f), 15.0f) - z) * sc;
        __half2 h0 = __floats2half2_rn(q0, q1);
        __half2 h1 = __floats2half2_rn(q2, q3);
        uint2 pk;
        pk.x = *reinterpret_cast<uint32_t*>(&h0);
        pk.y = *reinterpret_cast<uint32_t*>(&h1);
        reinterpret_cast<uint2*>(po)[i] = pk;
    }
}

// ---------------------------------------------------------------------------
// Legacy TF32 MMA GEMM — delta only (3xTF32 passes). Known-good from R2.
//   B layout [K,N] (N contiguous), EPI: D = acc + C[M,N] (C may alias D)
// ---------------------------------------------------------------------------
#define BK       32
#define ASTRIDE  36
#define BSTRIDE_KN 136
#define ASZ (128 * ASTRIDE)
#define BSZ (128 * ASTRIDE)
#define SMEM_BYTES ((2 * ASZ + 2 * BSZ) * 4)

__device__ __forceinline__ void cp16(uint32_t s, const void* g) {
    asm volatile("cp.async.cg.shared.global [%0], [%1], 16;\n" :: "r"(s), "l"(g));
}

__global__ __launch_bounds__(256, 2)
void gemm_delta_tf32(const float* __restrict__ A, const float* __restrict__ B,
                     const float* __restrict__ C, float* __restrict__ D,
                     int M, int N, int K) {
    extern __shared__ float sm[];
    float* As = sm;
    float* Bs = sm + 2 * ASZ;

    const int tid  = threadIdx.x;
    const int lane = tid & 31, warp = tid >> 5;
    const int grp  = lane >> 2, tig = lane & 3;
    const int wm   = warp & 3,  wn  = warp >> 2;
    const int mBase = blockIdx.y * 128, nBase = blockIdx.x * 128;

    const uint32_t sA = (uint32_t)__cvta_generic_to_shared(As);
    const uint32_t sB = (uint32_t)__cvta_generic_to_shared(Bs);

    float acc[2][8][4];
    #pragma unroll
    for (int i = 0; i < 2; i++)
        #pragma unroll
        for (int j = 0; j < 8; j++)
            #pragma unroll
            for (int k = 0; k < 4; k++) acc[i][j][k] = 0.0f;

    const int KT = K / BK;

    auto issue_tile = [&](int kt, int buf) {
        const float* ga = A + (size_t)mBase * K + (size_t)kt * BK;
        #pragma unroll
        for (int i = 0; i < 4; i++) {
            int idx = tid + i * 256;
            int r = idx >> 3, c = (idx & 7) << 2;
            cp16(sA + (uint32_t)((buf * ASZ + r * ASTRIDE + c) << 2),
                 ga + (size_t)r * K + c);
        }
        const float* gb = B + (size_t)(kt * BK) * N + nBase;
        #pragma unroll
        for (int i = 0; i < 4; i++) {
            int idx = tid + i * 256;
            int k = idx >> 5, c = (idx & 31) << 2;
            cp16(sB + (uint32_t)((buf * BSZ + k * BSTRIDE_KN + c) << 2),
                 gb + (size_t)k * N + c);
        }
        asm volatile("cp.async.commit_group;\n");
    };

    issue_tile(0, 0);

    for (int kt = 0; kt < KT; ++kt) {
        const int buf = kt & 1;
        if (kt + 1 < KT) {
            issue_tile(kt + 1, buf ^ 1);
            asm volatile("cp.async.wait_group 1;\n");
        } else {
            asm volatile("cp.async.wait_group 0;\n");
        }
        __syncthreads();

        const float* a = As + buf * ASZ;
        const float* b = Bs + buf * BSZ;

        #pragma unroll
        for (int ks = 0; ks < 4; ++ks) {
            const int kb = ks * 8;
            uint32_t b0[8], b1[8];
            #pragma unroll
            for (int ni = 0; ni < 8; ++ni) {
                const int n = wn * 64 + ni * 8 + grp;
                b0[ni] = __float_as_uint(b[(kb + tig)     * BSTRIDE_KN + n]);
                b1[ni] = __float_as_uint(b[(kb + 4 + tig) * BSTRIDE_KN + n]);
            }
            #pragma unroll
            for (int mi = 0; mi < 2; ++mi) {
                const int m = wm * 32 + mi * 16 + grp;
                uint32_t a0 = __float_as_uint(a[m       * ASTRIDE + kb + tig]);
                uint32_t a1 = __float_as_uint(a[(m + 8) * ASTRIDE + kb + tig]);
                uint32_t a2 = __float_as_uint(a[m       * ASTRIDE + kb + 4 + tig]);
                uint32_t a3 = __float_as_uint(a[(m + 8) * ASTRIDE + kb + 4 + tig]);
                #pragma unroll
                for (int ni = 0; ni < 8; ++ni) {
                    asm volatile(
                        "mma.sync.aligned.m16n8k8.row.col.f32.tf32.tf32.f32 "
                        "{%0,%1,%2,%3}, {%4,%5,%6,%7}, {%8,%9}, {%0,%1,%2,%3};\n"
                        : "+f"(acc[mi][ni][0]), "+f"(acc[mi][ni][1]),
                          "+f"(acc[mi][ni][2]), "+f"(acc[mi][ni][3])
                        : "r"(a0), "r"(a1), "r"(a2), "r"(a3),
                          "r"(b0[ni]), "r"(b1[ni]));
                }
            }
        }
        __syncthreads();
    }

    #pragma unroll
    for (int mi = 0; mi < 2; ++mi) {
        #pragma unroll
        for (int ni = 0; ni < 8; ++ni) {
            const int r0 = mBase + wm * 32 + mi * 16 + grp;
            const int cc = nBase + wn * 64 + ni * 8 + 2 * tig;
            float2 add0 = *reinterpret_cast<const float2*>(&C[(size_t)r0 * N + cc]);
            float2 add1 = *reinterpret_cast<const float2*>(&C[(size_t)(r0 + 8) * N + cc]);
            float2 o0 = make_float2(acc[mi][ni][0] + add0.x, acc[mi][ni][1] + add0.y);
            float2 o1 = make_float2(acc[mi][ni][2] + add1.x, acc[mi][ni][3] + add1.y);
            *reinterpret_cast<float2*>(&D[(size_t)r0 * N + cc])       = o0;
            *reinterpret_cast<float2*>(&D[(size_t)(r0 + 8) * N + cc]) = o1;
        }
    }
}

// ---------------------------------------------------------------------------
// Main GEMM: out[8192,11008] = xh[8192,4096] @ wh[11008,4096]^T + bias
// fp16 mma.sync.m16n8k16, ldmatrix fragment loads, CTA tile 128x256,
// 8 warps (2M x 4N), warp tile 64x64, 4-stage cp.async pipeline.
// smem rows padded to 80B (40 halves) -> conflict-free ldmatrix.
// ---------------------------------------------------------------------------
#define BM 128
#define BN 256
#define BKH 32                        // halves per K-tile
#define ROWB 80                       // padded row bytes (40 halves)
#define A_BYTES (BM * ROWB)           // 10240
#define B_BYTES (BN * ROWB)           // 20480
#define STAGE_BYTES (A_BYTES + B_BYTES)  // 30720
#define NSTAGE 4
#define MAIN_SMEM (NSTAGE * STAGE_BYTES) // 122880
#define KTILES (IN_DIM / BKH)         // 128

__device__ __forceinline__ void ldsm_x4(uint32_t* r, uint32_t addr) {
    asm volatile("ldmatrix.sync.aligned.m8n8.x4.shared.b16 {%0,%1,%2,%3}, [%4];"
                 : "=r"(r[0]), "=r"(r[1]), "=r"(r[2]), "=r"(r[3]) : "r"(addr));
}

__global__ __launch_bounds__(256, 1)
void gemm_main_fp16(const __half* __restrict__ xh, const __half* __restrict__ wh,
                    const float* __restrict__ bias, float* __restrict__ out) {
    extern __shared__ __align__(128) unsigned char smem[];
    const uint32_t sb = (uint32_t)__cvta_generic_to_shared(smem);
    const int tid = threadIdx.x, warp = tid >> 5, lane = tid & 31;
    const int wm = warp & 1, wn = warp >> 1;      // 2M x 4N warps

    // Grid swizzle: supercolumns of 8 N-tiles (43 N-tiles = 5*8 + 3)
    int g = blockIdx.x, mTile, nTile;
    if (g < 2560) { int grp = g >> 9, loc = g & 511; nTile = grp * 8 + (loc & 7); mTile = loc >> 3; }
    else          { int loc = g - 2560; nTile = 40 + loc % 3; mTile = loc / 3; }
    const int mBase = mTile * BM, nBase = nTile * BN;

    // cp.async assignments: 2 A chunks + 4 B chunks per thread (16B each)
    const __half* gA[2];
    uint32_t sAoff[2];
    #pragma unroll
    for (int i = 0; i < 2; i++) {
        int c = tid + i * 256;                 // 0..511
        int r = c >> 2, s = c & 3;
        gA[i] = xh + (size_t)(mBase + r) * IN_DIM + s * 8;
        sAoff[i] = r * ROWB + s * 16;
    }
    const __half* gB[4];
    uint32_t sBoff[4];
    #pragma unroll
    for (int i = 0; i < 4; i++) {
        int c = tid + i * 256;                 // 0..1023
        int r = c >> 2, s = c & 3;
        gB[i] = wh + (size_t)(nBase + r) * IN_DIM + s * 8;
        sBoff[i] = A_BYTES + r * ROWB + s * 16;
    }

    auto issue = [&](int kt) {
        const uint32_t base = sb + (uint32_t)(kt & (NSTAGE - 1)) * STAGE_BYTES;
        const int koff = kt * BKH;
        #pragma unroll
        for (int i = 0; i < 2; i++) cp16(base + sAoff[i], gA[i] + koff);
        #pragma unroll
        for (int i = 0; i < 4; i++) cp16(base + sBoff[i], gB[i] + koff);
        asm volatile("cp.async.commit_group;\n");
    };

    // ldmatrix per-thread base addressing
    // A mats: mat%2 -> m-half(+8), mat/2 -> k-half(+16B)
    const int mat = lane >> 3, mrow = lane & 7;
    const uint32_t aAddr0 = (uint32_t)(wm * 64 + ((mat & 1) << 3) + mrow) * ROWB
                          + ((mat >> 1) << 4);
    // B mats: mat/2 -> n-half(+8), mat%2 -> k-half(+16B)
    const uint32_t bAddr0 = A_BYTES
                          + (uint32_t)(wn * 64 + ((mat >> 1) << 3) + mrow) * ROWB
                          + ((mat & 1) << 4);

    float acc[4][8][4];
    #pragma unroll
    for (int i = 0; i < 4; i++)
        #pragma unroll
        for (int j = 0; j < 8; j++)
            #pragma unroll
            for (int k = 0; k < 4; k++) acc[i][j][k] = 0.0f;

    issue(0); issue(1); issue(2);

    for (int kt = 0; kt < KTILES; ++kt) {
        if (kt + 3 < KTILES) {
            issue(kt + 3);
            asm volatile("cp.async.wait_group 3;\n");
        } else {
            asm volatile("cp.async.wait_group 0;\n");
        }
        __syncthreads();

        const uint32_t base = sb + (uint32_t)(kt & (NSTAGE - 1)) * STAGE_BYTES;

        #pragma unroll
        for (int kk = 0; kk < 2; ++kk) {
            uint32_t af[4][4], bf[4][4];
            #pragma unroll
            for (int mi = 0; mi < 4; ++mi)
                ldsm_x4(af[mi], base + aAddr0 + mi * (16 * ROWB) + kk * 32);
            #pragma unroll
            for (int nj = 0; nj < 4; ++nj)
                ldsm_x4(bf[nj], base + bAddr0 + nj * (16 * ROWB) + kk * 32);
            #pragma unroll
            for (int mi = 0; mi < 4; ++mi) {
                #pragma unroll
                for (int nj = 0; nj < 4; ++nj) {
                    asm volatile(
                        "mma.sync.aligned.m16n8k16.row.col.f32.f16.f16.f32 "
                        "{%0,%1,%2,%3}, {%4,%5,%6,%7}, {%8,%9}, {%0,%1,%2,%3};\n"
                        : "+f"(acc[mi][nj*2][0]), "+f"(acc[mi][nj*2][1]),
                          "+f"(acc[mi][nj*2][2]), "+f"(acc[mi][nj*2][3])
                        : "r"(af[mi][0]), "r"(af[mi][1]), "r"(af[mi][2]), "r"(af[mi][3]),
                          "r"(bf[nj][0]), "r"(bf[nj][1]));
                    asm volatile(
                        "mma.sync.aligned.m16n8k16.row.col.f32.f16.f16.f32 "
                        "{%0,%1,%2,%3}, {%4,%5,%6,%7}, {%8,%9}, {%0,%1,%2,%3};\n"
                        : "+f"(acc[mi][nj*2+1][0]), "+f"(acc[mi][nj*2+1][1]),
                          "+f"(acc[mi][nj*2+1][2]), "+f"(acc[mi][nj*2+1][3])
                        : "r"(af[mi][0]), "r"(af[mi][1]), "r"(af[mi][2]), "r"(af[mi][3]),
                          "r"(bf[nj][2]), "r"(bf[nj][3]));
                }
            }
        }
        __syncthreads();
    }

    // Epilogue: acc[mi][njh]: m = mBase + wm*64 + mi*16 + lane/4 (+8 for c2,c3)
    //           n = nBase + wn*64 + njh*8 + (lane%4)*2
    const int mRow = mBase + wm * 64 + (lane >> 2);
    const int nCol = nBase + wn * 64 + ((lane & 3) << 1);
    #pragma unroll
    for (int mi = 0; mi < 4; ++mi) {
        const int m0 = mRow + mi * 16;
        #pragma unroll
        for (int njh = 0; njh < 8; ++njh) {
            const int n = nCol + njh * 8;
            float2 b2 = *reinterpret_cast<const float2*>(&bias[n]);
            float2 o0 = make_float2(acc[mi][njh][0] + b2.x, acc[mi][njh][1] + b2.y);
            float2 o1 = make_float2(acc[mi][njh][2] + b2.x, acc[mi][njh][3] + b2.y);
            *reinterpret_cast<float2*>(&out[(size_t)m0 * OUT_DIM + n])       = o0;
            *reinterpret_cast<float2*>(&out[(size_t)(m0 + 8) * OUT_DIM + n]) = o1;
        }
    }
}

// ---------------------------------------------------------------------------
// Launch
// ---------------------------------------------------------------------------
extern "C" void kernel_launch(void* const* d_in, const int* in_sizes, int n_in,
                              void* d_out, int out_size) {
    const float *x = nullptr, *weight = nullptr, *Bd = nullptr,
                *Bu = nullptr, *bias = nullptr;
    for (int i = 0; i < n_in; i++) {
        switch (in_sizes[i]) {
            case 33554432: x      = (const float*)d_in[i]; break;  // 8192*4096
            case 45088768: weight = (const float*)d_in[i]; break;  // 11008*4096
            case 2113536:  Bd     = (const float*)d_in[i]; break;  // 11008*192
            case 786432:   Bu     = (const float*)d_in[i]; break;  // 192*4096
            case 11008:    bias   = (const float*)d_in[i]; break;
        }
    }
    if (!x && n_in > 0)      x      = (const float*)d_in[0];
    if (!weight && n_in > 1) weight = (const float*)d_in[1];
    if (!Bd && n_in > 2)     Bd     = (const float*)d_in[2];
    if (!Bu && n_in > 3)     Bu     = (const float*)d_in[3];
    if (!bias && n_in > 4)   bias   = (const float*)d_in[4];

    float *gw, *gbdh, *gbdl, *gbuh, *gbul;
    __half *gxh, *gwh;
    cudaGetSymbolAddress((void**)&gw,   g_w);
    cudaGetSymbolAddress((void**)&gxh,  g_xh);
    cudaGetSymbolAddress((void**)&gwh,  g_wh);
    cudaGetSymbolAddress((void**)&gbdh, g_bd_hi);
    cudaGetSymbolAddress((void**)&gbdl, g_bd_lo);
    cudaGetSymbolAddress((void**)&gbuh, g_bu_hi);
    cudaGetSymbolAddress((void**)&gbul, g_bu_lo);

    cudaFuncSetAttribute(gemm_delta_tf32,
                         cudaFuncAttributeMaxDynamicSharedMemorySize, SMEM_BYTES);
    cudaFuncSetAttribute(gemm_main_fp16,
                         cudaFuncAttributeMaxDynamicSharedMemorySize, MAIN_SMEM);

    // 1) x -> fp16; Bd/Bu -> tf32 hi/lo splits
    cvt_half_kernel <<<(33554432 / 4 + 255) / 256, 256>>>(x, gxh, 33554432 / 4);
    cvt_split_kernel<<<(2113536  / 4 + 255) / 256, 256>>>(Bd, gbdh, gbdl, 2113536 / 4);
    cvt_split_kernel<<<(786432   / 4 + 255) / 256, 256>>>(Bu, gbuh, gbul, 786432  / 4);

    // 2) g_w = weight + Bd@Bu at fp32-equivalent precision (3xTF32)
    dim3 dgrid(IN_DIM / 128, OUT_DIM / 128);
    gemm_delta_tf32<<<dgrid, 256, SMEM_BYTES>>>(gbdh, gbuh, weight, gw,
                                                OUT_DIM, IN_DIM, RANK_);
    gemm_delta_tf32<<<dgrid, 256, SMEM_BYTES>>>(gbdh, gbul, gw, gw,
                                                OUT_DIM, IN_DIM, RANK_);
    gemm_delta_tf32<<<dgrid, 256, SMEM_BYTES>>>(gbdl, gbuh, gw, gw,
                                                OUT_DIM, IN_DIM, RANK_);

    // 3) fake-quant rows of g_w (fp32 decisions), emit fp16 g_wh
    quant_kernel<<<OUT_DIM, 256>>>(gw, gwh);

    // 4) out = xh @ wh^T + bias via fp16 m16n8k16
    gemm_main_fp16<<<2752, 256, MAIN_SMEM>>>(gxh, gwh, bias, (float*)d_out);
}

// round 5
// speedup vs baseline: 1.6630x; 1.0533x over previous
#include <cuda_runtime.h>
#include <cuda_fp16.h>
#include <cstdint>
#include <cstddef>

// Problem dims (fixed by the dataset)
#define M_DIM   8192      // 4*2048 rows of x
#define IN_DIM  4096      // K of main GEMM
#define OUT_DIM 11008     // N of main GEMM
#define RANK_   192

// ---------------------------------------------------------------------------
// Scratch (static __device__ arrays — allocation-free per harness rules)
// ---------------------------------------------------------------------------
__device__ __align__(256) float  g_w [(size_t)OUT_DIM * IN_DIM];  // weight+delta fp32
__device__ __align__(256) __half g_xh[(size_t)M_DIM  * IN_DIM];   // x as fp16
__device__ __align__(256) __half g_wh[(size_t)OUT_DIM * IN_DIM];  // quantized w as fp16

__device__ __forceinline__ float to_tf32(float x) {
    uint32_t u;
    asm("cvt.rna.tf32.f32 %0, %1;" : "=r"(u) : "f"(x));
    return __uint_as_float(u);
}

// ---------------------------------------------------------------------------
// x -> fp16
// ---------------------------------------------------------------------------
__global__ void cvt_half_kernel(const float* __restrict__ in,
                                __half* __restrict__ out, int n4) {
    int i = blockIdx.x * 256 + threadIdx.x;
    if (i < n4) {
        float4 v = reinterpret_cast<const float4*>(in)[i];
        __half2 h0 = __floats2half2_rn(v.x, v.y);
        __half2 h1 = __floats2half2_rn(v.z, v.w);
        uint2 p;
        p.x = *reinterpret_cast<uint32_t*>(&h0);
        p.y = *reinterpret_cast<uint32_t*>(&h1);
        reinterpret_cast<uint2*>(out)[i] = p;
    }
}

// ---------------------------------------------------------------------------
// Row-wise 4-bit asymmetric fake quant: read fp32 g_w, emit fp16 g_wh.
// ---------------------------------------------------------------------------
__global__ void quant_kernel(const float* __restrict__ w, __half* __restrict__ wh) {
    const int row = blockIdx.x;
    const float* p = w + (size_t)row * IN_DIM;
    __half* po = wh + (size_t)row * IN_DIM;
    const int tid = threadIdx.x;

    float mn = 0.0f, mx = 0.0f;   // init 0 implements min/max-with-0 clamp
    #pragma unroll
    for (int i = tid; i < IN_DIM / 4; i += 256) {
        float4 v = reinterpret_cast<const float4*>(p)[i];
        mn = fminf(mn, fminf(fminf(v.x, v.y), fminf(v.z, v.w)));
        mx = fmaxf(mx, fmaxf(fmaxf(v.x, v.y), fmaxf(v.z, v.w)));
    }
    #pragma unroll
    for (int o = 16; o; o >>= 1) {
        mn = fminf(mn, __shfl_xor_sync(0xffffffffu, mn, o));
        mx = fmaxf(mx, __shfl_xor_sync(0xffffffffu, mx, o));
    }
    __shared__ float smn[8], smx[8];
    __shared__ float s_scale, s_zero;
    const int warp = tid >> 5, lane = tid & 31;
    if (lane == 0) { smn[warp] = mn; smx[warp] = mx; }
    __syncthreads();
    if (tid == 0) {
        float a = smn[0], b = smx[0];
        #pragma unroll
        for (int i = 1; i < 8; i++) { a = fminf(a, smn[i]); b = fmaxf(b, smx[i]); }
        float sc = fmaxf((b - a) / 15.0f, 1e-8f);
        s_scale = sc;
        s_zero  = rintf(-a / sc);
    }
    __syncthreads();
    const float sc = s_scale, z = s_zero;

    #pragma unroll
    for (int i = tid; i < IN_DIM / 4; i += 256) {
        float4 v = reinterpret_cast<const float4*>(p)[i];
        float q0 = (fminf(fmaxf(rintf(v.x / sc) + z, 0.0f), 15.0f) - z) * sc;
        float q1 = (fminf(fmaxf(rintf(v.y / sc) + z, 0.0f), 15.0f) - z) * sc;
        float q2 = (fminf(fmaxf(rintf(v.z / sc) + z, 0.0f), 15.0f) - z) * sc;
        float q3 = (fminf(fmaxf(rintf(v.w / sc) + z, 0.0f), 15.0f) - z) * sc;
        __half2 h0 = __floats2half2_rn(q0, q1);
        __half2 h1 = __floats2half2_rn(q2, q3);
        uint2 pk;
        pk.x = *reinterpret_cast<uint32_t*>(&h0);
        pk.y = *reinterpret_cast<uint32_t*>(&h1);
        reinterpret_cast<uint2*>(po)[i] = pk;
    }
}

// ---------------------------------------------------------------------------
// FUSED delta GEMM (single pass, fp32-equivalent via 3xTF32 in-register):
//   D[M,N] = C[M,N] + A[M,K] @ B[K,N],  A=Bd fp32, B=Bu fp32, C=weight.
// Fragments loaded as fp32, split hi/lo with cvt.rna.tf32 in registers;
// accumulate ah*bh + ah*bl + al*bh per k-step (lo*lo dropped, ~2^-22 rel).
// Block tile 128x128x32, 8 warps (4M x 2N), warp tile 32x64. KT = 192/32 = 6.
// ---------------------------------------------------------------------------
#define BK       32
#define ASTRIDE  36
#define BSTRIDE_KN 136
#define ASZ (128 * ASTRIDE)
#define BSZ (128 * ASTRIDE)
#define SMEM_BYTES ((2 * ASZ + 2 * BSZ) * 4)   // 73728

__device__ __forceinline__ void cp16(uint32_t s, const void* g) {
    asm volatile("cp.async.cg.shared.global [%0], [%1], 16;\n" :: "r"(s), "l"(g));
}

__device__ __forceinline__ void mma_tf32(float* d, uint32_t a0, uint32_t a1,
                                         uint32_t a2, uint32_t a3,
                                         uint32_t b0, uint32_t b1) {
    asm volatile(
        "mma.sync.aligned.m16n8k8.row.col.f32.tf32.tf32.f32 "
        "{%0,%1,%2,%3}, {%4,%5,%6,%7}, {%8,%9}, {%0,%1,%2,%3};\n"
        : "+f"(d[0]), "+f"(d[1]), "+f"(d[2]), "+f"(d[3])
        : "r"(a0), "r"(a1), "r"(a2), "r"(a3), "r"(b0), "r"(b1));
}

__global__ __launch_bounds__(256, 2)
void gemm_delta_fused(const float* __restrict__ A, const float* __restrict__ B,
                      const float* __restrict__ C, float* __restrict__ D,
                      int M, int N, int K) {
    extern __shared__ float sm[];
    float* As = sm;
    float* Bs = sm + 2 * ASZ;

    const int tid  = threadIdx.x;
    const int lane = tid & 31, warp = tid >> 5;
    const int grp  = lane >> 2, tig = lane & 3;
    const int wm   = warp & 3,  wn  = warp >> 2;
    const int mBase = blockIdx.y * 128, nBase = blockIdx.x * 128;

    const uint32_t sA = (uint32_t)__cvta_generic_to_shared(As);
    const uint32_t sB = (uint32_t)__cvta_generic_to_shared(Bs);

    float acc[2][8][4];
    #pragma unroll
    for (int i = 0; i < 2; i++)
        #pragma unroll
        for (int j = 0; j < 8; j++)
            #pragma unroll
            for (int k = 0; k < 4; k++) acc[i][j][k] = 0.0f;

    const int KT = K / BK;   // 6

    auto issue_tile = [&](int kt, int buf) {
        const float* ga = A + (size_t)mBase * K + (size_t)kt * BK;
        #pragma unroll
        for (int i = 0; i < 4; i++) {
            int idx = tid + i * 256;
            int r = idx >> 3, c = (idx & 7) << 2;
            cp16(sA + (uint32_t)((buf * ASZ + r * ASTRIDE + c) << 2),
                 ga + (size_t)r * K + c);
        }
        const float* gb = B + (size_t)(kt * BK) * N + nBase;
        #pragma unroll
        for (int i = 0; i < 4; i++) {
            int idx = tid + i * 256;
            int k = idx >> 5, c = (idx & 31) << 2;
            cp16(sB + (uint32_t)((buf * BSZ + k * BSTRIDE_KN + c) << 2),
                 gb + (size_t)k * N + c);
        }
        asm volatile("cp.async.commit_group;\n");
    };

    issue_tile(0, 0);

    for (int kt = 0; kt < KT; ++kt) {
        const int buf = kt & 1;
        if (kt + 1 < KT) {
            issue_tile(kt + 1, buf ^ 1);
            asm volatile("cp.async.wait_group 1;\n");
        } else {
            asm volatile("cp.async.wait_group 0;\n");
        }
        __syncthreads();

        const float* a = As + buf * ASZ;
        const float* b = Bs + buf * BSZ;

        #pragma unroll
        for (int ks = 0; ks < 4; ++ks) {
            const int kb = ks * 8;
            // A fragments for both mi, split hi/lo
            uint32_t ah[2][4], al[2][4];
            #pragma unroll
            for (int mi = 0; mi < 2; ++mi) {
                const int m = wm * 32 + mi * 16 + grp;
                float v0 = a[m       * ASTRIDE + kb + tig];
                float v1 = a[(m + 8) * ASTRIDE + kb + tig];
                float v2 = a[m       * ASTRIDE + kb + 4 + tig];
                float v3 = a[(m + 8) * ASTRIDE + kb + 4 + tig];
                float h0 = to_tf32(v0), h1 = to_tf32(v1);
                float h2 = to_tf32(v2), h3 = to_tf32(v3);
                ah[mi][0] = __float_as_uint(h0); al[mi][0] = __float_as_uint(to_tf32(v0 - h0));
                ah[mi][1] = __float_as_uint(h1); al[mi][1] = __float_as_uint(to_tf32(v1 - h1));
                ah[mi][2] = __float_as_uint(h2); al[mi][2] = __float_as_uint(to_tf32(v2 - h2));
                ah[mi][3] = __float_as_uint(h3); al[mi][3] = __float_as_uint(to_tf32(v3 - h3));
            }
            // B fragments in two halves of 4 nj to limit registers
            #pragma unroll
            for (int nh = 0; nh < 2; ++nh) {
                uint32_t bh0[4], bl0[4], bh1[4], bl1[4];
                #pragma unroll
                for (int nj = 0; nj < 4; ++nj) {
                    const int n = wn * 64 + (nh * 4 + nj) * 8 + grp;
                    float v0 = b[(kb + tig)     * BSTRIDE_KN + n];
                    float v1 = b[(kb + 4 + tig) * BSTRIDE_KN + n];
                    float h0 = to_tf32(v0), h1 = to_tf32(v1);
                    bh0[nj] = __float_as_uint(h0); bl0[nj] = __float_as_uint(to_tf32(v0 - h0));
                    bh1[nj] = __float_as_uint(h1); bl1[nj] = __float_as_uint(to_tf32(v1 - h1));
                }
                #pragma unroll
                for (int mi = 0; mi < 2; ++mi) {
                    #pragma unroll
                    for (int nj = 0; nj < 4; ++nj) {
                        float* d = acc[mi][nh * 4 + nj];
                        // hi*hi
                        mma_tf32(d, ah[mi][0], ah[mi][1], ah[mi][2], ah[mi][3],
                                 bh0[nj], bh1[nj]);
                        // hi*lo
                        mma_tf32(d, ah[mi][0], ah[mi][1], ah[mi][2], ah[mi][3],
                                 bl0[nj], bl1[nj]);
                        // lo*hi
                        mma_tf32(d, al[mi][0], al[mi][1], al[mi][2], al[mi][3],
                                 bh0[nj], bh1[nj]);
                    }
                }
            }
        }
        __syncthreads();
    }

    #pragma unroll
    for (int mi = 0; mi < 2; ++mi) {
        #pragma unroll
        for (int ni = 0; ni < 8; ++ni) {
            const int r0 = mBase + wm * 32 + mi * 16 + grp;
            const int cc = nBase + wn * 64 + ni * 8 + 2 * tig;
            float2 add0 = *reinterpret_cast<const float2*>(&C[(size_t)r0 * N + cc]);
            float2 add1 = *reinterpret_cast<const float2*>(&C[(size_t)(r0 + 8) * N + cc]);
            float2 o0 = make_float2(acc[mi][ni][0] + add0.x, acc[mi][ni][1] + add0.y);
            float2 o1 = make_float2(acc[mi][ni][2] + add1.x, acc[mi][ni][3] + add1.y);
            *reinterpret_cast<float2*>(&D[(size_t)r0 * N + cc])       = o0;
            *reinterpret_cast<float2*>(&D[(size_t)(r0 + 8) * N + cc]) = o1;
        }
    }
}

// ---------------------------------------------------------------------------
// Main GEMM: out[8192,11008] = xh[8192,4096] @ wh[11008,4096]^T + bias
// fp16 mma.sync.m16n8k16, ldmatrix, CTA 128x256, 8 warps, 4-stage cp.async.
// (At legacy-HMMA issue ceiling; unchanged from R4.)
// ---------------------------------------------------------------------------
#define BM 128
#define BN 256
#define BKH 32
#define ROWB 80
#define A_BYTES (BM * ROWB)
#define B_BYTES (BN * ROWB)
#define STAGE_BYTES (A_BYTES + B_BYTES)
#define NSTAGE 4
#define MAIN_SMEM (NSTAGE * STAGE_BYTES)
#define KTILES (IN_DIM / BKH)

__device__ __forceinline__ void ldsm_x4(uint32_t* r, uint32_t addr) {
    asm volatile("ldmatrix.sync.aligned.m8n8.x4.shared.b16 {%0,%1,%2,%3}, [%4];"
                 : "=r"(r[0]), "=r"(r[1]), "=r"(r[2]), "=r"(r[3]) : "r"(addr));
}

__global__ __launch_bounds__(256, 1)
void gemm_main_fp16(const __half* __restrict__ xh, const __half* __restrict__ wh,
                    const float* __restrict__ bias, float* __restrict__ out) {
    extern __shared__ __align__(128) unsigned char smem[];
    const uint32_t sb = (uint32_t)__cvta_generic_to_shared(smem);
    const int tid = threadIdx.x, warp = tid >> 5, lane = tid & 31;
    const int wm = warp & 1, wn = warp >> 1;

    int g = blockIdx.x, mTile, nTile;
    if (g < 2560) { int grp = g >> 9, loc = g & 511; nTile = grp * 8 + (loc & 7); mTile = loc >> 3; }
    else          { int loc = g - 2560; nTile = 40 + loc % 3; mTile = loc / 3; }
    const int mBase = mTile * BM, nBase = nTile * BN;

    const __half* gA[2];
    uint32_t sAoff[2];
    #pragma unroll
    for (int i = 0; i < 2; i++) {
        int c = tid + i * 256;
        int r = c >> 2, s = c & 3;
        gA[i] = xh + (size_t)(mBase + r) * IN_DIM + s * 8;
        sAoff[i] = r * ROWB + s * 16;
    }
    const __half* gB[4];
    uint32_t sBoff[4];
    #pragma unroll
    for (int i = 0; i < 4; i++) {
        int c = tid + i * 256;
        int r = c >> 2, s = c & 3;
        gB[i] = wh + (size_t)(nBase + r) * IN_DIM + s * 8;
        sBoff[i] = A_BYTES + r * ROWB + s * 16;
    }

    auto issue = [&](int kt) {
        const uint32_t base = sb + (uint32_t)(kt & (NSTAGE - 1)) * STAGE_BYTES;
        const int koff = kt * BKH;
        #pragma unroll
        for (int i = 0; i < 2; i++) cp16(base + sAoff[i], gA[i] + koff);
        #pragma unroll
        for (int i = 0; i < 4; i++) cp16(base + sBoff[i], gB[i] + koff);
        asm volatile("cp.async.commit_group;\n");
    };

    const int mat = lane >> 3, mrow = lane & 7;
    const uint32_t aAddr0 = (uint32_t)(wm * 64 + ((mat & 1) << 3) + mrow) * ROWB
                          + ((mat >> 1) << 4);
    const uint32_t bAddr0 = A_BYTES
                          + (uint32_t)(wn * 64 + ((mat >> 1) << 3) + mrow) * ROWB
                          + ((mat & 1) << 4);

    float acc[4][8][4];
    #pragma unroll
    for (int i = 0; i < 4; i++)
        #pragma unroll
        for (int j = 0; j < 8; j++)
            #pragma unroll
            for (int k = 0; k < 4; k++) acc[i][j][k] = 0.0f;

    issue(0); issue(1); issue(2);

    for (int kt = 0; kt < KTILES; ++kt) {
        if (kt + 3 < KTILES) {
            issue(kt + 3);
            asm volatile("cp.async.wait_group 3;\n");
        } else {
            asm volatile("cp.async.wait_group 0;\n");
        }
        __syncthreads();

        const uint32_t base = sb + (uint32_t)(kt & (NSTAGE - 1)) * STAGE_BYTES;

        #pragma unroll
        for (int kk = 0; kk < 2; ++kk) {
            uint32_t af[4][4], bf[4][4];
            #pragma unroll
            for (int mi = 0; mi < 4; ++mi)
                ldsm_x4(af[mi], base + aAddr0 + mi * (16 * ROWB) + kk * 32);
            #pragma unroll
            for (int nj = 0; nj < 4; ++nj)
                ldsm_x4(bf[nj], base + bAddr0 + nj * (16 * ROWB) + kk * 32);
            #pragma unroll
            for (int mi = 0; mi < 4; ++mi) {
                #pragma unroll
                for (int nj = 0; nj < 4; ++nj) {
                    asm volatile(
                        "mma.sync.aligned.m16n8k16.row.col.f32.f16.f16.f32 "
                        "{%0,%1,%2,%3}, {%4,%5,%6,%7}, {%8,%9}, {%0,%1,%2,%3};\n"
                        : "+f"(acc[mi][nj*2][0]), "+f"(acc[mi][nj*2][1]),
                          "+f"(acc[mi][nj*2][2]), "+f"(acc[mi][nj*2][3])
                        : "r"(af[mi][0]), "r"(af[mi][1]), "r"(af[mi][2]), "r"(af[mi][3]),
                          "r"(bf[nj][0]), "r"(bf[nj][1]));
                    asm volatile(
                        "mma.sync.aligned.m16n8k16.row.col.f32.f16.f16.f32 "
                        "{%0,%1,%2,%3}, {%4,%5,%6,%7}, {%8,%9}, {%0,%1,%2,%3};\n"
                        : "+f"(acc[mi][nj*2+1][0]), "+f"(acc[mi][nj*2+1][1]),
                          "+f"(acc[mi][nj*2+1][2]), "+f"(acc[mi][nj*2+1][3])
                        : "r"(af[mi][0]), "r"(af[mi][1]), "r"(af[mi][2]), "r"(af[mi][3]),
                          "r"(bf[nj][2]), "r"(bf[nj][3]));
                }
            }
        }
        __syncthreads();
    }

    const int mRow = mBase + wm * 64 + (lane >> 2);
    const int nCol = nBase + wn * 64 + ((lane & 3) << 1);
    #pragma unroll
    for (int mi = 0; mi < 4; ++mi) {
        const int m0 = mRow + mi * 16;
        #pragma unroll
        for (int njh = 0; njh < 8; ++njh) {
            const int n = nCol + njh * 8;
            float2 b2 = *reinterpret_cast<const float2*>(&bias[n]);
            float2 o0 = make_float2(acc[mi][njh][0] + b2.x, acc[mi][njh][1] + b2.y);
            float2 o1 = make_float2(acc[mi][njh][2] + b2.x, acc[mi][njh][3] + b2.y);
            *reinterpret_cast<float2*>(&out[(size_t)m0 * OUT_DIM + n])       = o0;
            *reinterpret_cast<float2*>(&out[(size_t)(m0 + 8) * OUT_DIM + n]) = o1;
        }
    }
}

// ---------------------------------------------------------------------------
// Launch
// ---------------------------------------------------------------------------
extern "C" void kernel_launch(void* const* d_in, const int* in_sizes, int n_in,
                              void* d_out, int out_size) {
    const float *x = nullptr, *weight = nullptr, *Bd = nullptr,
                *Bu = nullptr, *bias = nullptr;
    for (int i = 0; i < n_in; i++) {
        switch (in_sizes[i]) {
            case 33554432: x      = (const float*)d_in[i]; break;  // 8192*4096
            case 45088768: weight = (const float*)d_in[i]; break;  // 11008*4096
            case 2113536:  Bd     = (const float*)d_in[i]; break;  // 11008*192
            case 786432:   Bu     = (const float*)d_in[i]; break;  // 192*4096
            case 11008:    bias   = (const float*)d_in[i]; break;
        }
    }
    if (!x && n_in > 0)      x      = (const float*)d_in[0];
    if (!weight && n_in > 1) weight = (const float*)d_in[1];
    if (!Bd && n_in > 2)     Bd     = (const float*)d_in[2];
    if (!Bu && n_in > 3)     Bu     = (const float*)d_in[3];
    if (!bias && n_in > 4)   bias   = (const float*)d_in[4];

    float *gw;
    __half *gxh, *gwh;
    cudaGetSymbolAddress((void**)&gw,  g_w);
    cudaGetSymbolAddress((void**)&gxh, g_xh);
    cudaGetSymbolAddress((void**)&gwh, g_wh);

    cudaFuncSetAttribute(gemm_delta_fused,
                         cudaFuncAttributeMaxDynamicSharedMemorySize, SMEM_BYTES);
    cudaFuncSetAttribute(gemm_main_fp16,
                         cudaFuncAttributeMaxDynamicSharedMemorySize, MAIN_SMEM);

    // 1) x -> fp16
    cvt_half_kernel<<<(33554432 / 4 + 255) / 256, 256>>>(x, gxh, 33554432 / 4);

    // 2) g_w = weight + Bd@Bu (single fused pass, fp32-equivalent 3xTF32)
    gemm_delta_fused<<<dim3(IN_DIM / 128, OUT_DIM / 128), 256, SMEM_BYTES>>>(
        Bd, Bu, weight, gw, OUT_DIM, IN_DIM, RANK_);

    // 3) fake-quant rows of g_w (fp32 decisions), emit fp16 g_wh
    quant_kernel<<<OUT_DIM, 256>>>(gw, gwh);

    // 4) out = xh @ wh^T + bias via fp16 m16n8k16
    gemm_main_fp16<<<2752, 256, MAIN_SMEM>>>(gxh, gwh, bias, (float*)d_out);
}

// round 6
// speedup vs baseline: 1.7124x; 1.0297x over previous
#include <cuda_runtime.h>
#include <cuda_fp16.h>
#include <cstdint>
#include <cstddef>

// Problem dims (fixed by the dataset)
#define M_DIM   8192      // 4*2048 rows of x
#define IN_DIM  4096      // K of main GEMM
#define OUT_DIM 11008     // N of main GEMM
#define RANK_   192

// ---------------------------------------------------------------------------
// Scratch (static __device__ arrays — allocation-free per harness rules)
// ---------------------------------------------------------------------------
__device__ __align__(256) float  g_w [(size_t)OUT_DIM * IN_DIM];  // weight+delta fp32
__device__ __align__(256) __half g_xh[(size_t)M_DIM  * IN_DIM];   // x as fp16
__device__ __align__(256) __half g_wh[(size_t)OUT_DIM * IN_DIM];  // quantized w as fp16

__device__ __forceinline__ float to_tf32(float x) {
    uint32_t u;
    asm("cvt.rna.tf32.f32 %0, %1;" : "=r"(u) : "f"(x));
    return __uint_as_float(u);
}

// ---------------------------------------------------------------------------
// x -> fp16
// ---------------------------------------------------------------------------
__global__ void cvt_half_kernel(const float* __restrict__ in,
                                __half* __restrict__ out, int n4) {
    int i = blockIdx.x * 256 + threadIdx.x;
    if (i < n4) {
        float4 v = reinterpret_cast<const float4*>(in)[i];
        __half2 h0 = __floats2half2_rn(v.x, v.y);
        __half2 h1 = __floats2half2_rn(v.z, v.w);
        uint2 p;
        p.x = *reinterpret_cast<uint32_t*>(&h0);
        p.y = *reinterpret_cast<uint32_t*>(&h1);
        reinterpret_cast<uint2*>(out)[i] = p;
    }
}

// ---------------------------------------------------------------------------
// Row-wise 4-bit asymmetric fake quant: read fp32 g_w, emit fp16 g_wh.
// ---------------------------------------------------------------------------
__global__ void quant_kernel(const float* __restrict__ w, __half* __restrict__ wh) {
    const int row = blockIdx.x;
    const float* p = w + (size_t)row * IN_DIM;
    __half* po = wh + (size_t)row * IN_DIM;
    const int tid = threadIdx.x;

    float mn = 0.0f, mx = 0.0f;   // init 0 implements min/max-with-0 clamp
    #pragma unroll
    for (int i = tid; i < IN_DIM / 4; i += 256) {
        float4 v = reinterpret_cast<const float4*>(p)[i];
        mn = fminf(mn, fminf(fminf(v.x, v.y), fminf(v.z, v.w)));
        mx = fmaxf(mx, fmaxf(fmaxf(v.x, v.y), fmaxf(v.z, v.w)));
    }
    #pragma unroll
    for (int o = 16; o; o >>= 1) {
        mn = fminf(mn, __shfl_xor_sync(0xffffffffu, mn, o));
        mx = fmaxf(mx, __shfl_xor_sync(0xffffffffu, mx, o));
    }
    __shared__ float smn[8], smx[8];
    __shared__ float s_scale, s_zero;
    const int warp = tid >> 5, lane = tid & 31;
    if (lane == 0) { smn[warp] = mn; smx[warp] = mx; }
    __syncthreads();
    if (tid == 0) {
        float a = smn[0], b = smx[0];
        #pragma unroll
        for (int i = 1; i < 8; i++) { a = fminf(a, smn[i]); b = fmaxf(b, smx[i]); }
        float sc = fmaxf((b - a) / 15.0f, 1e-8f);
        s_scale = sc;
        s_zero  = rintf(-a / sc);
    }
    __syncthreads();
    const float sc = s_scale, z = s_zero;

    #pragma unroll
    for (int i = tid; i < IN_DIM / 4; i += 256) {
        float4 v = reinterpret_cast<const float4*>(p)[i];
        float q0 = (fminf(fmaxf(rintf(v.x / sc) + z, 0.0f), 15.0f) - z) * sc;
        float q1 = (fminf(fmaxf(rintf(v.y / sc) + z, 0.0f), 15.0f) - z) * sc;
        float q2 = (fminf(fmaxf(rintf(v.z / sc) + z, 0.0f), 15.0f) - z) * sc;
        float q3 = (fminf(fmaxf(rintf(v.w / sc) + z, 0.0f), 15.0f) - z) * sc;
        __half2 h0 = __floats2half2_rn(q0, q1);
        __half2 h1 = __floats2half2_rn(q2, q3);
        uint2 pk;
        pk.x = *reinterpret_cast<uint32_t*>(&h0);
        pk.y = *reinterpret_cast<uint32_t*>(&h1);
        reinterpret_cast<uint2*>(po)[i] = pk;
    }
}

// ---------------------------------------------------------------------------
// FUSED delta GEMM (single pass, fp32-equivalent via 3xTF32 in-register):
//   D[M,N] = C[M,N] + A[M,K] @ B[K,N],  A=Bd fp32, B=Bu fp32, C=weight.
// ---------------------------------------------------------------------------
#define BK       32
#define ASTRIDE  36
#define BSTRIDE_KN 136
#define ASZ (128 * ASTRIDE)
#define BSZ (128 * ASTRIDE)
#define SMEM_BYTES ((2 * ASZ + 2 * BSZ) * 4)   // 73728

__device__ __forceinline__ void cp16(uint32_t s, const void* g) {
    asm volatile("cp.async.cg.shared.global [%0], [%1], 16;\n" :: "r"(s), "l"(g));
}

__device__ __forceinline__ void mma_tf32(float* d, uint32_t a0, uint32_t a1,
                                         uint32_t a2, uint32_t a3,
                                         uint32_t b0, uint32_t b1) {
    asm volatile(
        "mma.sync.aligned.m16n8k8.row.col.f32.tf32.tf32.f32 "
        "{%0,%1,%2,%3}, {%4,%5,%6,%7}, {%8,%9}, {%0,%1,%2,%3};\n"
        : "+f"(d[0]), "+f"(d[1]), "+f"(d[2]), "+f"(d[3])
        : "r"(a0), "r"(a1), "r"(a2), "r"(a3), "r"(b0), "r"(b1));
}

__global__ __launch_bounds__(256, 2)
void gemm_delta_fused(const float* __restrict__ A, const float* __restrict__ B,
                      const float* __restrict__ C, float* __restrict__ D,
                      int M, int N, int K) {
    extern __shared__ float sm[];
    float* As = sm;
    float* Bs = sm + 2 * ASZ;

    const int tid  = threadIdx.x;
    const int lane = tid & 31, warp = tid >> 5;
    const int grp  = lane >> 2, tig = lane & 3;
    const int wm   = warp & 3,  wn  = warp >> 2;
    const int mBase = blockIdx.y * 128, nBase = blockIdx.x * 128;

    const uint32_t sA = (uint32_t)__cvta_generic_to_shared(As);
    const uint32_t sB = (uint32_t)__cvta_generic_to_shared(Bs);

    float acc[2][8][4];
    #pragma unroll
    for (int i = 0; i < 2; i++)
        #pragma unroll
        for (int j = 0; j < 8; j++)
            #pragma unroll
            for (int k = 0; k < 4; k++) acc[i][j][k] = 0.0f;

    const int KT = K / BK;   // 6

    auto issue_tile = [&](int kt, int buf) {
        const float* ga = A + (size_t)mBase * K + (size_t)kt * BK;
        #pragma unroll
        for (int i = 0; i < 4; i++) {
            int idx = tid + i * 256;
            int r = idx >> 3, c = (idx & 7) << 2;
            cp16(sA + (uint32_t)((buf * ASZ + r * ASTRIDE + c) << 2),
                 ga + (size_t)r * K + c);
        }
        const float* gb = B + (size_t)(kt * BK) * N + nBase;
        #pragma unroll
        for (int i = 0; i < 4; i++) {
            int idx = tid + i * 256;
            int k = idx >> 5, c = (idx & 31) << 2;
            cp16(sB + (uint32_t)((buf * BSZ + k * BSTRIDE_KN + c) << 2),
                 gb + (size_t)k * N + c);
        }
        asm volatile("cp.async.commit_group;\n");
    };

    issue_tile(0, 0);

    for (int kt = 0; kt < KT; ++kt) {
        const int buf = kt & 1;
        if (kt + 1 < KT) {
            issue_tile(kt + 1, buf ^ 1);
            asm volatile("cp.async.wait_group 1;\n");
        } else {
            asm volatile("cp.async.wait_group 0;\n");
        }
        __syncthreads();

        const float* a = As + buf * ASZ;
        const float* b = Bs + buf * BSZ;

        #pragma unroll
        for (int ks = 0; ks < 4; ++ks) {
            const int kb = ks * 8;
            uint32_t ah[2][4], al[2][4];
            #pragma unroll
            for (int mi = 0; mi < 2; ++mi) {
                const int m = wm * 32 + mi * 16 + grp;
                float v0 = a[m       * ASTRIDE + kb + tig];
                float v1 = a[(m + 8) * ASTRIDE + kb + tig];
                float v2 = a[m       * ASTRIDE + kb + 4 + tig];
                float v3 = a[(m + 8) * ASTRIDE + kb + 4 + tig];
                float h0 = to_tf32(v0), h1 = to_tf32(v1);
                float h2 = to_tf32(v2), h3 = to_tf32(v3);
                ah[mi][0] = __float_as_uint(h0); al[mi][0] = __float_as_uint(to_tf32(v0 - h0));
                ah[mi][1] = __float_as_uint(h1); al[mi][1] = __float_as_uint(to_tf32(v1 - h1));
                ah[mi][2] = __float_as_uint(h2); al[mi][2] = __float_as_uint(to_tf32(v2 - h2));
                ah[mi][3] = __float_as_uint(h3); al[mi][3] = __float_as_uint(to_tf32(v3 - h3));
            }
            #pragma unroll
            for (int nh = 0; nh < 2; ++nh) {
                uint32_t bh0[4], bl0[4], bh1[4], bl1[4];
                #pragma unroll
                for (int nj = 0; nj < 4; ++nj) {
                    const int n = wn * 64 + (nh * 4 + nj) * 8 + grp;
                    float v0 = b[(kb + tig)     * BSTRIDE_KN + n];
                    float v1 = b[(kb + 4 + tig) * BSTRIDE_KN + n];
                    float h0 = to_tf32(v0), h1 = to_tf32(v1);
                    bh0[nj] = __float_as_uint(h0); bl0[nj] = __float_as_uint(to_tf32(v0 - h0));
                    bh1[nj] = __float_as_uint(h1); bl1[nj] = __float_as_uint(to_tf32(v1 - h1));
                }
                #pragma unroll
                for (int mi = 0; mi < 2; ++mi) {
                    #pragma unroll
                    for (int nj = 0; nj < 4; ++nj) {
                        float* d = acc[mi][nh * 4 + nj];
                        mma_tf32(d, ah[mi][0], ah[mi][1], ah[mi][2], ah[mi][3],
                                 bh0[nj], bh1[nj]);
                        mma_tf32(d, ah[mi][0], ah[mi][1], ah[mi][2], ah[mi][3],
                                 bl0[nj], bl1[nj]);
                        mma_tf32(d, al[mi][0], al[mi][1], al[mi][2], al[mi][3],
                                 bh0[nj], bh1[nj]);
                    }
                }
            }
        }
        __syncthreads();
    }

    #pragma unroll
    for (int mi = 0; mi < 2; ++mi) {
        #pragma unroll
        for (int ni = 0; ni < 8; ++ni) {
            const int r0 = mBase + wm * 32 + mi * 16 + grp;
            const int cc = nBase + wn * 64 + ni * 8 + 2 * tig;
            float2 add0 = *reinterpret_cast<const float2*>(&C[(size_t)r0 * N + cc]);
            float2 add1 = *reinterpret_cast<const float2*>(&C[(size_t)(r0 + 8) * N + cc]);
            float2 o0 = make_float2(acc[mi][ni][0] + add0.x, acc[mi][ni][1] + add0.y);
            float2 o1 = make_float2(acc[mi][ni][2] + add1.x, acc[mi][ni][3] + add1.y);
            *reinterpret_cast<float2*>(&D[(size_t)r0 * N + cc])       = o0;
            *reinterpret_cast<float2*>(&D[(size_t)(r0 + 8) * N + cc]) = o1;
        }
    }
}

// ---------------------------------------------------------------------------
// Main GEMM: out[8192,11008] = xh[8192,4096] @ wh[11008,4096]^T + bias
// fp16 mma.sync.m16n8k16, ldmatrix, CTA 128x256, 8 warps, 4-stage cp.async.
// R6: single __syncthreads per k-tile + fragment double-buffering.
// ---------------------------------------------------------------------------
#define BM 128
#define BN 256
#define BKH 32
#define ROWB 80
#define A_BYTES (BM * ROWB)
#define B_BYTES (BN * ROWB)
#define STAGE_BYTES (A_BYTES + B_BYTES)
#define NSTAGE 4
#define MAIN_SMEM (NSTAGE * STAGE_BYTES)
#define KTILES (IN_DIM / BKH)

__device__ __forceinline__ void ldsm_x4(uint32_t* r, uint32_t addr) {
    asm volatile("ldmatrix.sync.aligned.m8n8.x4.shared.b16 {%0,%1,%2,%3}, [%4];"
                 : "=r"(r[0]), "=r"(r[1]), "=r"(r[2]), "=r"(r[3]) : "r"(addr));
}

__device__ __forceinline__ void mma_f16(float* d, const uint32_t* a,
                                        uint32_t b0, uint32_t b1) {
    asm volatile(
        "mma.sync.aligned.m16n8k16.row.col.f32.f16.f16.f32 "
        "{%0,%1,%2,%3}, {%4,%5,%6,%7}, {%8,%9}, {%0,%1,%2,%3};\n"
        : "+f"(d[0]), "+f"(d[1]), "+f"(d[2]), "+f"(d[3])
        : "r"(a[0]), "r"(a[1]), "r"(a[2]), "r"(a[3]), "r"(b0), "r"(b1));
}

__global__ __launch_bounds__(256, 1)
void gemm_main_fp16(const __half* __restrict__ xh, const __half* __restrict__ wh,
                    const float* __restrict__ bias, float* __restrict__ out) {
    extern __shared__ __align__(128) unsigned char smem[];
    const uint32_t sb = (uint32_t)__cvta_generic_to_shared(smem);
    const int tid = threadIdx.x, warp = tid >> 5, lane = tid & 31;
    const int wm = warp & 1, wn = warp >> 1;

    int g = blockIdx.x, mTile, nTile;
    if (g < 2560) { int grp = g >> 9, loc = g & 511; nTile = grp * 8 + (loc & 7); mTile = loc >> 3; }
    else          { int loc = g - 2560; nTile = 40 + loc % 3; mTile = loc / 3; }
    const int mBase = mTile * BM, nBase = nTile * BN;

    const __half* gA[2];
    uint32_t sAoff[2];
    #pragma unroll
    for (int i = 0; i < 2; i++) {
        int c = tid + i * 256;
        int r = c >> 2, s = c & 3;
        gA[i] = xh + (size_t)(mBase + r) * IN_DIM + s * 8;
        sAoff[i] = r * ROWB + s * 16;
    }
    const __half* gB[4];
    uint32_t sBoff[4];
    #pragma unroll
    for (int i = 0; i < 4; i++) {
        int c = tid + i * 256;
        int r = c >> 2, s = c & 3;
        gB[i] = wh + (size_t)(nBase + r) * IN_DIM + s * 8;
        sBoff[i] = A_BYTES + r * ROWB + s * 16;
    }

    auto issue = [&](int kt) {
        const uint32_t base = sb + (uint32_t)(kt & (NSTAGE - 1)) * STAGE_BYTES;
        const int koff = kt * BKH;
        #pragma unroll
        for (int i = 0; i < 2; i++) cp16(base + sAoff[i], gA[i] + koff);
        #pragma unroll
        for (int i = 0; i < 4; i++) cp16(base + sBoff[i], gB[i] + koff);
        asm volatile("cp.async.commit_group;\n");
    };

    const int mat = lane >> 3, mrow = lane & 7;
    const uint32_t aAddr0 = (uint32_t)(wm * 64 + ((mat & 1) << 3) + mrow) * ROWB
                          + ((mat >> 1) << 4);
    const uint32_t bAddr0 = A_BYTES
                          + (uint32_t)(wn * 64 + ((mat >> 1) << 3) + mrow) * ROWB
                          + ((mat & 1) << 4);

    float acc[4][8][4];
    #pragma unroll
    for (int i = 0; i < 4; i++)
        #pragma unroll
        for (int j = 0; j < 8; j++)
            #pragma unroll
            for (int k = 0; k < 4; k++) acc[i][j][k] = 0.0f;

    issue(0); issue(1); issue(2);

    uint32_t af[2][4][4], bf[2][4][4];

    for (int kt = 0; kt < KTILES; ++kt) {
        // Wait until stage kt's cp.async group has landed (exact tail counts).
        if (kt < KTILES - 2)       { asm volatile("cp.async.wait_group 2;\n"); }
        else if (kt == KTILES - 2) { asm volatile("cp.async.wait_group 1;\n"); }
        else                       { asm volatile("cp.async.wait_group 0;\n"); }
        __syncthreads();
        // Refill stage (kt+3)&3 == (kt-1)&3: all warps passed the barrier, so
        // every reader of that stage (iteration kt-1) is done. One sync/iter.
        if (kt + 3 < KTILES) issue(kt + 3);

        const uint32_t base = sb + (uint32_t)(kt & (NSTAGE - 1)) * STAGE_BYTES;

        // Load BOTH kk halves' fragments up front: the kk=1 LDSM batch
        // overlaps the kk=0 MMA block (no load-use chain inside a half).
        #pragma unroll
        for (int kk = 0; kk < 2; ++kk) {
            #pragma unroll
            for (int mi = 0; mi < 4; ++mi)
                ldsm_x4(af[kk][mi], base + aAddr0 + mi * (16 * ROWB) + kk * 32);
            #pragma unroll
            for (int nj = 0; nj < 4; ++nj)
                ldsm_x4(bf[kk][nj], base + bAddr0 + nj * (16 * ROWB) + kk * 32);
        }
        #pragma unroll
        for (int kk = 0; kk < 2; ++kk) {
            #pragma unroll
            for (int mi = 0; mi < 4; ++mi) {
                #pragma unroll
                for (int nj = 0; nj < 4; ++nj) {
                    mma_f16(acc[mi][nj * 2],     af[kk][mi], bf[kk][nj][0], bf[kk][nj][1]);
                    mma_f16(acc[mi][nj * 2 + 1], af[kk][mi], bf[kk][nj][2], bf[kk][nj][3]);
                }
            }
        }
    }

    const int mRow = mBase + wm * 64 + (lane >> 2);
    const int nCol = nBase + wn * 64 + ((lane & 3) << 1);
    #pragma unroll
    for (int mi = 0; mi < 4; ++mi) {
        const int m0 = mRow + mi * 16;
        #pragma unroll
        for (int njh = 0; njh < 8; ++njh) {
            const int n = nCol + njh * 8;
            float2 b2 = *reinterpret_cast<const float2*>(&bias[n]);
            float2 o0 = make_float2(acc[mi][njh][0] + b2.x, acc[mi][njh][1] + b2.y);
            float2 o1 = make_float2(acc[mi][njh][2] + b2.x, acc[mi][njh][3] + b2.y);
            *reinterpret_cast<float2*>(&out[(size_t)m0 * OUT_DIM + n])       = o0;
            *reinterpret_cast<float2*>(&out[(size_t)(m0 + 8) * OUT_DIM + n]) = o1;
        }
    }
}

// ---------------------------------------------------------------------------
// Launch
// ---------------------------------------------------------------------------
extern "C" void kernel_launch(void* const* d_in, const int* in_sizes, int n_in,
                              void* d_out, int out_size) {
    const float *x = nullptr, *weight = nullptr, *Bd = nullptr,
                *Bu = nullptr, *bias = nullptr;
    for (int i = 0; i < n_in; i++) {
        switch (in_sizes[i]) {
            case 33554432: x      = (const float*)d_in[i]; break;  // 8192*4096
            case 45088768: weight = (const float*)d_in[i]; break;  // 11008*4096
            case 2113536:  Bd     = (const float*)d_in[i]; break;  // 11008*192
            case 786432:   Bu     = (const float*)d_in[i]; break;  // 192*4096
            case 11008:    bias   = (const float*)d_in[i]; break;
        }
    }
    if (!x && n_in > 0)      x      = (const float*)d_in[0];
    if (!weight && n_in > 1) weight = (const float*)d_in[1];
    if (!Bd && n_in > 2)     Bd     = (const float*)d_in[2];
    if (!Bu && n_in > 3)     Bu     = (const float*)d_in[3];
    if (!bias && n_in > 4)   bias   = (const float*)d_in[4];

    float *gw;
    __half *gxh, *gwh;
    cudaGetSymbolAddress((void**)&gw,  g_w);
    cudaGetSymbolAddress((void**)&gxh, g_xh);
    cudaGetSymbolAddress((void**)&gwh, g_wh);

    cudaFuncSetAttribute(gemm_delta_fused,
                         cudaFuncAttributeMaxDynamicSharedMemorySize, SMEM_BYTES);
    cudaFuncSetAttribute(gemm_main_fp16,
                         cudaFuncAttributeMaxDynamicSharedMemorySize, MAIN_SMEM);

    // 1) x -> fp16
    cvt_half_kernel<<<(33554432 / 4 + 255) / 256, 256>>>(x, gxh, 33554432 / 4);

    // 2) g_w = weight + Bd@Bu (single fused pass, fp32-equivalent 3xTF32)
    gemm_delta_fused<<<dim3(IN_DIM / 128, OUT_DIM / 128), 256, SMEM_BYTES>>>(
        Bd, Bu, weight, gw, OUT_DIM, IN_DIM, RANK_);

    // 3) fake-quant rows of g_w (fp32 decisions), emit fp16 g_wh
    quant_kernel<<<OUT_DIM, 256>>>(gw, gwh);

    // 4) out = xh @ wh^T + bias via fp16 m16n8k16
    gemm_main_fp16<<<2752, 256, MAIN_SMEM>>>(gxh, gwh, bias, (float*)d_out);
}